// round 1
// baseline (speedup 1.0000x reference)
#include <cuda_runtime.h>

// Conv_12060268167596: per-channel 5x5 correlation, stride=1, pad=2.
// X: [4,32,512,512] f32 -> treat as 128 independent 512x512 planes.
// kernel: [5,5] f32 shared across all planes.
// Output: same shape as X.
//
// Tiled smem kernel: block (32,8) -> output tile 128x8 per block.
// Smem tile (128+4) x (8+4) = 132x12 floats (halo 2 on each side).
// Each thread computes 4 contiguous outputs (float4 store) via a 5-tap
// sliding window: per kernel row, two LDS.128 give 8 floats, reused for
// all 4 outputs. 25 weights live in registers (uniform LDG, L1-resident).

#define IMG 512
#define TXD 32
#define TYD 8
#define OUTX 128          // TXD * 4 outputs per row per block
#define SW (OUTX + 4)     // 132
#define SH (TYD + 4)      // 12

__global__ __launch_bounds__(TXD * TYD) void conv5x5_kernel(
    const float* __restrict__ X,
    const float* __restrict__ Kw,
    float* __restrict__ Out)
{
    __shared__ float s[SH * SW];

    const int c   = blockIdx.z;                 // plane index (b*32 + ch)
    const int gx0 = blockIdx.x * OUTX;
    const int gy0 = blockIdx.y * TYD;
    const float* __restrict__ Xc = X + (size_t)c * (IMG * IMG);

    // ---- cooperative tile load (with zero halo fill) ----
    const int tid = threadIdx.y * TXD + threadIdx.x;
    #pragma unroll 2
    for (int idx = tid; idx < SH * SW; idx += TXD * TYD) {
        const int sy = idx / SW;
        const int sx = idx - sy * SW;
        const int gy = gy0 + sy - 2;
        const int gx = gx0 + sx - 2;
        float v = 0.0f;
        if ((unsigned)gy < (unsigned)IMG && (unsigned)gx < (unsigned)IMG)
            v = __ldg(&Xc[gy * IMG + gx]);
        s[idx] = v;
    }

    // ---- weights to registers (uniform address -> broadcast, L1 hit) ----
    float w[25];
    #pragma unroll
    for (int i = 0; i < 25; i++) w[i] = __ldg(&Kw[i]);

    __syncthreads();

    // ---- compute 4 outputs per thread (sliding 5-tap window) ----
    const int tx = threadIdx.x;
    const int ty = threadIdx.y;

    float acc0 = 0.f, acc1 = 0.f, acc2 = 0.f, acc3 = 0.f;

    #pragma unroll
    for (int r = 0; r < 5; r++) {
        const float* row = &s[(ty + r) * SW + tx * 4];
        const float4 a = *reinterpret_cast<const float4*>(row);
        const float4 b = *reinterpret_cast<const float4*>(row + 4);
        const float v0 = a.x, v1 = a.y, v2 = a.z, v3 = a.w;
        const float v4 = b.x, v5 = b.y, v6 = b.z, v7 = b.w;

        const float w0 = w[r * 5 + 0];
        const float w1 = w[r * 5 + 1];
        const float w2 = w[r * 5 + 2];
        const float w3 = w[r * 5 + 3];
        const float w4 = w[r * 5 + 4];

        acc0 = fmaf(w0, v0, acc0); acc1 = fmaf(w0, v1, acc1);
        acc2 = fmaf(w0, v2, acc2); acc3 = fmaf(w0, v3, acc3);
        acc0 = fmaf(w1, v1, acc0); acc1 = fmaf(w1, v2, acc1);
        acc2 = fmaf(w1, v3, acc2); acc3 = fmaf(w1, v4, acc3);
        acc0 = fmaf(w2, v2, acc0); acc1 = fmaf(w2, v3, acc1);
        acc2 = fmaf(w2, v4, acc2); acc3 = fmaf(w2, v5, acc3);
        acc0 = fmaf(w3, v3, acc0); acc1 = fmaf(w3, v4, acc1);
        acc2 = fmaf(w3, v5, acc2); acc3 = fmaf(w3, v6, acc3);
        acc0 = fmaf(w4, v4, acc0); acc1 = fmaf(w4, v5, acc1);
        acc2 = fmaf(w4, v6, acc2); acc3 = fmaf(w4, v7, acc3);
    }

    const int gx = gx0 + tx * 4;
    const int gy = gy0 + ty;
    float4 o;
    o.x = acc0; o.y = acc1; o.z = acc2; o.w = acc3;
    *reinterpret_cast<float4*>(&Out[(size_t)c * (IMG * IMG) + gy * IMG + gx]) = o;
}

extern "C" void kernel_launch(void* const* d_in, const int* in_sizes, int n_in,
                              void* d_out, int out_size)
{
    const float* X  = (const float*)d_in[0];
    const float* Kw = (const float*)d_in[1];
    float* Out      = (float*)d_out;

    // 128 planes of 512x512; 512/128 = 4 tiles in x, 512/8 = 64 in y.
    dim3 grid(IMG / OUTX, IMG / TYD, 128);
    dim3 block(TXD, TYD);
    conv5x5_kernel<<<grid, block>>>(X, Kw, Out);
}

// round 2
// speedup vs baseline: 1.2660x; 1.2660x over previous
#include <cuda_runtime.h>

// Per-channel 5x5 correlation, stride=1, pad=2 over 128 planes of 512x512 f32.
// Block (16,8)=128 threads; each thread computes an 8x4 output micro-tile.
// Block output tile: 128 x 32. Smem tile 136 x 36 floats (halo 4 in x for
// float4 alignment, halo 2 in y), 19.6 KB.
// Every global fill load is an aligned float4 that is fully in or fully out
// of bounds -> pure LDG.128/STS.128, no per-element predication, no divides.

#define IMG 512
#define BX 16
#define BY 8
#define OX 8               // outputs per thread in x
#define OY 4               // outputs per thread in y
#define TILE_X (BX * OX)   // 128
#define TILE_Y (BY * OY)   // 32
#define SW 136             // TILE_X + 8 (4-aligned halo both sides)
#define SH (TILE_Y + 4)    // 36
#define NVX (SW / 4)       // 34 float4 columns

__global__ __launch_bounds__(BX * BY) void conv5x5_kernel(
    const float* __restrict__ X,
    const float* __restrict__ Kw,
    float* __restrict__ Out)
{
    __shared__ float s[SH * SW];

    const int c   = blockIdx.z;
    const int gx0 = blockIdx.x * TILE_X;
    const int gy0 = blockIdx.y * TILE_Y;
    const float* __restrict__ Xc = X + (size_t)c * (IMG * IMG);

    const int tx = threadIdx.x;   // 0..15
    const int ty = threadIdx.y;   // 0..7

    // ---- tile fill: aligned float4 loads, full in/out predication ----
    // smem x-base corresponds to global x = gx0 - 4 (16B aligned since gx0 % 128 == 0)
    // smem y-base corresponds to global y = gy0 - 2
    #pragma unroll
    for (int sy = ty; sy < SH; sy += BY) {
        const int gy = gy0 + sy - 2;
        const bool yin = (unsigned)gy < (unsigned)IMG;
        const float* rowp = Xc + (size_t)gy * IMG;
        #pragma unroll
        for (int vx = tx; vx < NVX; vx += BX) {
            const int gx = gx0 + vx * 4 - 4;
            float4 v = make_float4(0.f, 0.f, 0.f, 0.f);
            if (yin && (unsigned)gx < (unsigned)IMG)   // 4-aligned: fully in or out
                v = *reinterpret_cast<const float4*>(rowp + gx);
            *reinterpret_cast<float4*>(&s[sy * SW + vx * 4]) = v;
        }
    }

    // ---- weights to registers ----
    float w[25];
    #pragma unroll
    for (int i = 0; i < 25; i++) w[i] = __ldg(&Kw[i]);

    __syncthreads();

    // ---- compute 8x4 micro-tile ----
    const int sy0 = ty * OY;          // first output row (local)
    const int sx0 = tx * OX;          // smem float index of 16-float window base
                                      // (covers input x = gx0 + sx0 - 4 .. +11)
    float acc[OY][OX];
    #pragma unroll
    for (int i = 0; i < OY; i++)
        #pragma unroll
        for (int j = 0; j < OX; j++) acc[i][j] = 0.f;

    #pragma unroll
    for (int r = 0; r < OY + 4; r++) {      // 8 input rows
        const float* row = &s[(sy0 + r) * SW + sx0];
        float v[16];
        #pragma unroll
        for (int q = 0; q < 4; q++) {
            const float4 t4 = *reinterpret_cast<const float4*>(row + q * 4);
            v[q * 4 + 0] = t4.x; v[q * 4 + 1] = t4.y;
            v[q * 4 + 2] = t4.z; v[q * 4 + 3] = t4.w;
        }
        #pragma unroll
        for (int i = 0; i < OY; i++) {
            const int kr = r - i;                 // kernel row for output row i
            if (kr < 0 || kr > 4) continue;       // resolved at compile time
            #pragma unroll
            for (int t = 0; t < 5; t++) {
                const float wv = w[kr * 5 + t];
                #pragma unroll
                for (int j = 0; j < OX; j++)
                    acc[i][j] = fmaf(wv, v[j + 2 + t], acc[i][j]);
            }
        }
    }

    // ---- store 8x4 outputs (2 x STG.128 per row) ----
    float* Oc = Out + (size_t)c * (IMG * IMG);
    #pragma unroll
    for (int i = 0; i < OY; i++) {
        const int gy = gy0 + sy0 + i;
        float* op = Oc + (size_t)gy * IMG + gx0 + sx0;
        float4 o0, o1;
        o0.x = acc[i][0]; o0.y = acc[i][1]; o0.z = acc[i][2]; o0.w = acc[i][3];
        o1.x = acc[i][4]; o1.y = acc[i][5]; o1.z = acc[i][6]; o1.w = acc[i][7];
        *reinterpret_cast<float4*>(op)     = o0;
        *reinterpret_cast<float4*>(op + 4) = o1;
    }
}

extern "C" void kernel_launch(void* const* d_in, const int* in_sizes, int n_in,
                              void* d_out, int out_size)
{
    const float* X  = (const float*)d_in[0];
    const float* Kw = (const float*)d_in[1];
    float* Out      = (float*)d_out;

    dim3 grid(IMG / TILE_X, IMG / TILE_Y, 128);   // 4 x 16 x 128
    dim3 block(BX, BY);
    conv5x5_kernel<<<grid, block>>>(X, Kw, Out);
}

// round 3
// speedup vs baseline: 1.4512x; 1.1463x over previous
#include <cuda_runtime.h>

// Per-channel 5x5 correlation, stride=1, pad=2; 128 planes of 512x512 f32.
// Shared-memory-free register-rolling kernel:
//   - warp owns a 256-wide x 32-row strip; lane owns 8 consecutive x.
//   - per input row: 2 aligned LDG.128 (own 8 floats) + 4 warp shuffles for
//     the +-2 x halo (warp-edge lanes load tiny predicated float2 from gmem).
//   - each input row loaded ONCE, accumulated into the 5 pending output rows
//     kept in registers (mod-5 slot rotation, compile-time via unroll-5).
//   - packed f32x2 FMA: 4 output pairs x 25 taps = 100 FMA2 per row-step.

#define IMG  512
#define R    32            // output rows per warp strip
#define FULLMASK 0xffffffffu

__device__ __forceinline__ unsigned long long pk(float lo, float hi) {
    unsigned long long r;
    asm("mov.b64 %0, {%1, %2};" : "=l"(r) : "f"(lo), "f"(hi));
    return r;
}
__device__ __forceinline__ void upk(unsigned long long v, float& lo, float& hi) {
    asm("mov.b64 {%0, %1}, %2;" : "=f"(lo), "=f"(hi) : "l"(v));
}
__device__ __forceinline__ unsigned long long fma2(unsigned long long a,
                                                   unsigned long long b,
                                                   unsigned long long c) {
    unsigned long long d;
    asm("fma.rn.f32x2 %0, %1, %2, %3;" : "=l"(d) : "l"(a), "l"(b), "l"(c));
    return d;
}

// All 25 taps of input-row (s) into the 5 pending output slots.
// I = s mod 5 (compile-time). out[j] += w[kr][t] * v[j+t]; pairs p[q]=(v[q],v[q+1]).
template<int I>
__device__ __forceinline__ void accstep(unsigned long long acc[5][4],
                                        const unsigned long long* __restrict__ wp,
                                        const unsigned long long* __restrict__ p) {
    #pragma unroll
    for (int kr = 0; kr < 5; kr++) {
        const int slot = ((I - kr) % 5 + 5) % 5;   // compile-time after unroll
        #pragma unroll
        for (int t = 0; t < 5; t++) {
            #pragma unroll
            for (int pj = 0; pj < 4; pj++)
                acc[slot][pj] = fma2(wp[kr * 5 + t], p[2 * pj + t], acc[slot][pj]);
        }
    }
}

__global__ __launch_bounds__(128) void conv5x5_kernel(
    const float* __restrict__ X,
    const float* __restrict__ Kw,
    float* __restrict__ Out)
{
    const int lane  = threadIdx.x;                  // 0..31
    const int wrp   = threadIdx.y;                  // 0..3
    const int c     = blockIdx.z;                   // plane
    const int warpX = blockIdx.x;                   // 0..1  (x half)
    const int strip = blockIdx.y * 4 + wrp;         // 0..15 (y strip)
    const int Y0    = strip * R;
    const int x0    = warpX * 256 + lane * 8;

    const float* __restrict__ Xc = X   + (size_t)c * (IMG * IMG);
    float*       __restrict__ Oc = Out + (size_t)c * (IMG * IMG);

    // packed (w,w) weights
    unsigned long long wp[25];
    #pragma unroll
    for (int i = 0; i < 25; i++) { const float wv = __ldg(&Kw[i]); wp[i] = pk(wv, wv); }

    unsigned long long acc[5][4];
    #pragma unroll
    for (int j = 0; j < 5; j++)
        #pragma unroll
        for (int q = 0; q < 4; q++) acc[j][q] = 0ull;

    unsigned long long p[11];   // packed sliding-window pairs of current input row

// Load input row for step S into raw regs (zero outside image).
#define LOADROW(S, A, B, LF, RF) do {                                          \
    const int gy_ = Y0 - 2 + (S);                                              \
    (A) = make_float4(0.f,0.f,0.f,0.f); (B) = make_float4(0.f,0.f,0.f,0.f);    \
    (LF) = make_float2(0.f,0.f); (RF) = make_float2(0.f,0.f);                  \
    if ((unsigned)gy_ < (unsigned)IMG) {                                       \
        const float* rp_ = Xc + (size_t)gy_ * IMG + x0;                        \
        (A) = *reinterpret_cast<const float4*>(rp_);                           \
        (B) = *reinterpret_cast<const float4*>(rp_ + 4);                       \
        if (lane == 0  && x0 >= 2)      (LF) = *reinterpret_cast<const float2*>(rp_ - 2); \
        if (lane == 31 && x0 + 9 < IMG) (RF) = *reinterpret_cast<const float2*>(rp_ + 8); \
    }                                                                          \
} while (0)

// Shuffle halo + pack row into p[0..10].  v = [l0,l1,A.xyzw,B.xyzw,r0,r1]
#define PACKROW(A, B, LF, RF) do {                                             \
    float l0_ = __shfl_up_sync(FULLMASK,  (B).z, 1);                           \
    float l1_ = __shfl_up_sync(FULLMASK,  (B).w, 1);                           \
    float r0_ = __shfl_down_sync(FULLMASK,(A).x, 1);                           \
    float r1_ = __shfl_down_sync(FULLMASK,(A).y, 1);                           \
    if (lane == 0)  { l0_ = (LF).x; l1_ = (LF).y; }                            \
    if (lane == 31) { r0_ = (RF).x; r1_ = (RF).y; }                            \
    p[0]  = pk(l0_,  l1_ );  p[1]  = pk(l1_,  (A).x);                          \
    p[2]  = pk((A).x,(A).y); p[3]  = pk((A).y,(A).z);                          \
    p[4]  = pk((A).z,(A).w); p[5]  = pk((A).w,(B).x);                          \
    p[6]  = pk((B).x,(B).y); p[7]  = pk((B).y,(B).z);                          \
    p[8]  = pk((B).z,(B).w); p[9]  = pk((B).w, r0_ );                          \
    p[10] = pk(r0_,  r1_ );                                                    \
} while (0)

// One pipeline step: prefetch row s+1, FMA row s (in p), store completed row,
// reset its slot, then pack row s+1 into p.  I == s mod 5 (literal).
#define STEP(I, LAST) do {                                                     \
    const int s_ = sb + (I);                                                   \
    float4 A_, B_; float2 LF_, RF_;                                            \
    if (!(LAST)) LOADROW(s_ + 1, A_, B_, LF_, RF_);                            \
    accstep<(I)>(acc, wp, p);                                                  \
    if ((I) >= 4 || sb >= 4) {                                                 \
        const int o_ = s_ - 4;                                                 \
        float r0,r1,r2,r3,r4,r5,r6,r7;                                         \
        upk(acc[((I)+1)%5][0], r0, r1);                                        \
        upk(acc[((I)+1)%5][1], r2, r3);                                        \
        upk(acc[((I)+1)%5][2], r4, r5);                                        \
        upk(acc[((I)+1)%5][3], r6, r7);                                        \
        float* op_ = Oc + (size_t)(Y0 + o_) * IMG + x0;                        \
        *reinterpret_cast<float4*>(op_)     = make_float4(r0,r1,r2,r3);        \
        *reinterpret_cast<float4*>(op_ + 4) = make_float4(r4,r5,r6,r7);        \
    }                                                                          \
    acc[((I)+1)%5][0] = 0ull; acc[((I)+1)%5][1] = 0ull;                        \
    acc[((I)+1)%5][2] = 0ull; acc[((I)+1)%5][3] = 0ull;                        \
    if (!(LAST)) PACKROW(A_, B_, LF_, RF_);                                    \
} while (0)

    // prologue: row 0 into p
    {
        float4 A0, B0; float2 LF0, RF0;
        LOADROW(0, A0, B0, LF0, RF0);
        PACKROW(A0, B0, LF0, RF0);
    }

    // steps 0..34 in unroll-5 blocks (sb multiple of 5 -> slots compile-time)
    for (int sb = 0; sb < 35; sb += 5) {
        STEP(0, false);
        STEP(1, false);
        STEP(2, false);
        STEP(3, false);
        STEP(4, false);
    }
    // final step s = 35 (35 mod 5 == 0), no prefetch
    {
        const int sb = 35;
        STEP(0, true);
    }

#undef STEP
#undef PACKROW
#undef LOADROW
}

extern "C" void kernel_launch(void* const* d_in, const int* in_sizes, int n_in,
                              void* d_out, int out_size)
{
    const float* X  = (const float*)d_in[0];
    const float* Kw = (const float*)d_in[1];
    float* Out      = (float*)d_out;

    dim3 grid(2, 4, 128);       // x halves, strip groups (4 strips/block), planes
    dim3 block(32, 4);          // 4 warps, each owns one 256x32 strip
    conv5x5_kernel<<<grid, block>>>(X, Kw, Out);
}